// round 7
// baseline (speedup 1.0000x reference)
#include <cuda_runtime.h>

// RotationPerturbationLayer == bilinear sampling with zero padding.
//
// R6 change: amortize per-pixel overhead. Each thread computes 4 consecutive
// x-pixels of one row:
//   - theta load + __sincosf + base coordinate math once per 4 pixels
//     (sx steps by +cos, sy by -sin per x increment: 2 FADDs/pixel)
//   - stores vectorized: 3x STG.128 instead of 12x STG.32
//   - grid 128 -> 32 CTAs (fewer dispatches)
// Invalid taps handled branch-free: weight zeroed (SEL), address clamped.
//
// B=8, C=3, H=W=64.  8192 threads = 32 blocks x 256.

#define BB 8
#define CC 3
#define HH 64
#define WW 64
#define NN (HH * WW)   // 4096

__global__ __launch_bounds__(256, 1)
void rotation_bilinear4_kernel(const float* __restrict__ theta,
                               const float* __restrict__ image,
                               float* __restrict__ out)
{
    const int idx = blockIdx.x * blockDim.x + threadIdx.x;  // 0 .. B*N/4-1
    const int b   = idx >> 10;          // / (NN/4)
    const int rem = idx & 1023;
    const int y   = rem >> 4;           // / (WW/4)
    const int x4  = (rem & 15) << 2;    // starting x (multiple of 4)

    const float t = __ldg(theta + b);
    float st, ct;
    __sincosf(t, &st, &ct);

    const float c_x = (WW - 1) * 0.5f;
    const float c_y = (HH - 1) * 0.5f;
    const float xr = (float)x4 - c_x;
    const float yr = (float)y  - c_y;

    // Base source coords for pixel x4; step by (+ct, -st) per x increment.
    float sx =  ct * xr + st * yr + c_x;
    float sy = -st * xr + ct * yr + c_y;

    float4 o0, o1, o2;  // per-channel outputs for the 4 pixels
    float* const po0 = &o0.x;
    float* const po1 = &o1.x;
    float* const po2 = &o2.x;

    #pragma unroll
    for (int j = 0; j < 4; j++) {
        const float fx = floorf(sx);
        const float fy = floorf(sy);
        const int x0 = (int)fx;
        const int y0 = (int)fy;
        const int x1 = x0 + 1;
        const int y1 = y0 + 1;

        const float axw = sx - fx;
        const float ayw = sy - fy;

        const float bxv = ((unsigned)x0 < (unsigned)WW) ? (1.0f - axw) : 0.0f;
        const float axv = ((unsigned)x1 < (unsigned)WW) ? axw          : 0.0f;
        const float byv = ((unsigned)y0 < (unsigned)HH) ? (1.0f - ayw) : 0.0f;
        const float ayv = ((unsigned)y1 < (unsigned)HH) ? ayw          : 0.0f;

        const int x0c = min(max(x0, 0), WW - 1);
        const int x1c = min(max(x1, 0), WW - 1);
        const int y0c = min(max(y0, 0), HH - 1);
        const int y1c = min(max(y1, 0), HH - 1);

        const int p00 = y0c * WW + x0c;
        const int p01 = y0c * WW + x1c;
        const int p10 = y1c * WW + x0c;
        const int p11 = y1c * WW + x1c;

        const float w00 = byv * bxv;
        const float w01 = byv * axv;
        const float w10 = ayv * bxv;
        const float w11 = ayv * axv;

        po0[j] = w00 * __ldg(image + p00)
               + w01 * __ldg(image + p01)
               + w10 * __ldg(image + p10)
               + w11 * __ldg(image + p11);
        po1[j] = w00 * __ldg(image + NN + p00)
               + w01 * __ldg(image + NN + p01)
               + w10 * __ldg(image + NN + p10)
               + w11 * __ldg(image + NN + p11);
        po2[j] = w00 * __ldg(image + 2 * NN + p00)
               + w01 * __ldg(image + 2 * NN + p01)
               + w10 * __ldg(image + 2 * NN + p10)
               + w11 * __ldg(image + 2 * NN + p11);

        sx += ct;   // next x pixel
        sy -= st;
    }

    // out [B, C, H, W]; x4 is 16B-aligned within the row -> STG.128.
    const int n = y * WW + x4;
    float4* ob = (float4*)(out + b * (CC * NN) + n);
    ob[0]              = o0;
    ob[NN / 4]         = o1;
    ob[2 * (NN / 4)]   = o2;
}

extern "C" void kernel_launch(void* const* d_in, const int* in_sizes, int n_in,
                              void* d_out, int out_size)
{
    const float* theta = (const float*)d_in[0];  // [B,1] = 8 floats
    const float* image = (const float*)d_in[1];  // [C,H,W] = 12288 floats
    float* out = (float*)d_out;                  // [B,C,H,W] = 98304 floats

    rotation_bilinear4_kernel<<<(BB * NN / 4) / 256, 256>>>(theta, image, out);
}

// round 8
// speedup vs baseline: 1.1953x; 1.1953x over previous
#include <cuda_runtime.h>

// RotationPerturbationLayer == bilinear sampling with zero padding.
//
// R7: keep the proven R3 shape (1 pixel/thread, 128 CTAs x 256, single wave)
// but split interior vs edge:
//   - interior (x0 in [0,W-2], y0 in [0,H-2], ~94% of pixels, whole warps):
//     straight-line path, no clamps, no per-tap predicates, 12 batched LDGs.
//   - edge ring: general path with per-tap weight zeroing + clamped address.
// One branch region instead of four; __float2int_rd for the floor.

#define BB 8
#define CC 3
#define HH 64
#define WW 64
#define NN (HH * WW)   // 4096

__global__ __launch_bounds__(256, 1)
void rotation_bilinear_kernel(const float* __restrict__ theta,
                              const float* __restrict__ image,
                              float* __restrict__ out)
{
    const int idx = blockIdx.x * blockDim.x + threadIdx.x;  // 0 .. B*N-1
    const int b = idx >> 12;
    const int n = idx & (NN - 1);
    const int y = n >> 6;
    const int x = n & (WW - 1);

    const float t = __ldg(theta + b);
    float st, ct;
    __sincosf(t, &st, &ct);

    const float c_x = (WW - 1) * 0.5f;
    const float c_y = (HH - 1) * 0.5f;
    const float xr = (float)x - c_x;
    const float yr = (float)y - c_y;

    const float sx = fmaf(ct, xr, fmaf(st, yr, c_x));
    const float sy = fmaf(-st, xr, fmaf(ct, yr, c_y));

    const int x0 = __float2int_rd(sx);
    const int y0 = __float2int_rd(sy);

    const float ax = sx - (float)x0;   // weight toward x0+1
    const float ay = sy - (float)y0;

    float acc0, acc1, acc2;

    if (((unsigned)x0 < (WW - 1)) & ((unsigned)y0 < (HH - 1))) {
        // ---- interior fast path: all 4 taps valid, no clamping ----
        const float bx = 1.0f - ax;
        const float by = 1.0f - ay;
        const float w00 = by * bx;
        const float w01 = by * ax;
        const float w10 = ay * bx;
        const float w11 = ay * ax;

        const int p00 = y0 * WW + x0;          // p01 = p00+1, p1x = p00+WW
        const float* i0 = image + p00;
        const float* i1 = i0 + NN;
        const float* i2 = i1 + NN;

        acc0 = w00 * __ldg(i0)      + w01 * __ldg(i0 + 1)
             + w10 * __ldg(i0 + WW) + w11 * __ldg(i0 + WW + 1);
        acc1 = w00 * __ldg(i1)      + w01 * __ldg(i1 + 1)
             + w10 * __ldg(i1 + WW) + w11 * __ldg(i1 + WW + 1);
        acc2 = w00 * __ldg(i2)      + w01 * __ldg(i2 + 1)
             + w10 * __ldg(i2 + WW) + w11 * __ldg(i2 + WW + 1);
    } else {
        // ---- edge path: zero weights for invalid taps, clamp addresses ----
        const int x1 = x0 + 1;
        const int y1 = y0 + 1;
        const float bxv = ((unsigned)x0 < (unsigned)WW) ? (1.0f - ax) : 0.0f;
        const float axv = ((unsigned)x1 < (unsigned)WW) ? ax          : 0.0f;
        const float byv = ((unsigned)y0 < (unsigned)HH) ? (1.0f - ay) : 0.0f;
        const float ayv = ((unsigned)y1 < (unsigned)HH) ? ay          : 0.0f;

        const int x0c = min(max(x0, 0), WW - 1);
        const int x1c = min(max(x1, 0), WW - 1);
        const int y0c = min(max(y0, 0), HH - 1);
        const int y1c = min(max(y1, 0), HH - 1);

        const int p00 = y0c * WW + x0c;
        const int p01 = y0c * WW + x1c;
        const int p10 = y1c * WW + x0c;
        const int p11 = y1c * WW + x1c;

        const float w00 = byv * bxv;
        const float w01 = byv * axv;
        const float w10 = ayv * bxv;
        const float w11 = ayv * axv;

        acc0 = w00 * __ldg(image + p00) + w01 * __ldg(image + p01)
             + w10 * __ldg(image + p10) + w11 * __ldg(image + p11);
        acc1 = w00 * __ldg(image + NN + p00) + w01 * __ldg(image + NN + p01)
             + w10 * __ldg(image + NN + p10) + w11 * __ldg(image + NN + p11);
        acc2 = w00 * __ldg(image + 2 * NN + p00) + w01 * __ldg(image + 2 * NN + p01)
             + w10 * __ldg(image + 2 * NN + p10) + w11 * __ldg(image + 2 * NN + p11);
    }

    // out [B, C, H, W]; per-channel writes warp-contiguous.
    float* ob = out + b * (CC * NN) + n;
    ob[0]      = acc0;
    ob[NN]     = acc1;
    ob[2 * NN] = acc2;
}

extern "C" void kernel_launch(void* const* d_in, const int* in_sizes, int n_in,
                              void* d_out, int out_size)
{
    const float* theta = (const float*)d_in[0];  // [B,1]
    const float* image = (const float*)d_in[1];  // [C,H,W]
    float* out = (float*)d_out;                  // [B,C,H,W]

    rotation_bilinear_kernel<<<(BB * NN) / 256, 256>>>(theta, image, out);
}

// round 10
// speedup vs baseline: 1.3179x; 1.1026x over previous
#include <cuda_runtime.h>

// RotationPerturbationLayer == bilinear sampling with zero padding (the dense
// [B,N,N] tent-weight einsum has <=4 nonzero taps per output coordinate;
// taps outside [0,W)x[0,H) contribute zero).
//
// R9 == R8 resubmit (R8 hit an infra failure, never ran). Champion R3 shape —
// 1 pixel/thread, 128 CTAs x 256 (single wave), nested per-tap ifs (near-zero
// real divergence, smallest code) — with dependent-chain trims:
//   - __float2int_rd instead of floorf + cast
//   - explicit fmaf for the rotation
//   - output offset via idx + (b << 13), no extra IMAD
//   - channel-plane base pointers hoisted

#define BB 8
#define CC 3
#define HH 64
#define WW 64
#define NN (HH * WW)   // 4096

__global__ __launch_bounds__(256, 1)
void rotation_bilinear_kernel(const float* __restrict__ theta,
                              const float* __restrict__ image,
                              float* __restrict__ out)
{
    const int idx = blockIdx.x * blockDim.x + threadIdx.x;  // 0 .. B*N-1
    const int b = idx >> 12;        // / NN
    const int n = idx & (NN - 1);   // % NN
    const int y = n >> 6;           // / WW
    const int x = n & (WW - 1);     // % WW

    const float t = __ldg(theta + b);   // 8 distinct values, L2-broadcast
    float st, ct;
    __sincosf(t, &st, &ct);

    const float c_x = (WW - 1) * 0.5f;
    const float c_y = (HH - 1) * 0.5f;
    const float xr = (float)x - c_x;
    const float yr = (float)y - c_y;

    const float sx = fmaf(ct, xr, fmaf(st, yr, c_x));
    const float sy = fmaf(-st, xr, fmaf(ct, yr, c_y));

    const int x0 = __float2int_rd(sx);
    const int y0 = __float2int_rd(sy);
    const int x1 = x0 + 1;
    const int y1 = y0 + 1;

    const float ax = sx - (float)x0;   // tent weight toward x1
    const float ay = sy - (float)y0;
    const float bx = 1.0f - ax;        // tent weight toward x0
    const float by = 1.0f - ay;

    const bool vx0 = (unsigned)x0 < (unsigned)WW;
    const bool vx1 = (unsigned)x1 < (unsigned)WW;
    const bool vy0 = (unsigned)y0 < (unsigned)HH;
    const bool vy1 = (unsigned)y1 < (unsigned)HH;

    const float* img1 = image + NN;
    const float* img2 = image + 2 * NN;

    float acc0 = 0.0f, acc1 = 0.0f, acc2 = 0.0f;

    if (vy0) {
        const int row = y0 * WW;
        if (vx0) {
            const float w = by * bx;
            const int p = row + x0;
            acc0 = fmaf(w, __ldg(image + p), acc0);
            acc1 = fmaf(w, __ldg(img1 + p),  acc1);
            acc2 = fmaf(w, __ldg(img2 + p),  acc2);
        }
        if (vx1) {
            const float w = by * ax;
            const int p = row + x1;
            acc0 = fmaf(w, __ldg(image + p), acc0);
            acc1 = fmaf(w, __ldg(img1 + p),  acc1);
            acc2 = fmaf(w, __ldg(img2 + p),  acc2);
        }
    }
    if (vy1) {
        const int row = y1 * WW;
        if (vx0) {
            const float w = ay * bx;
            const int p = row + x0;
            acc0 = fmaf(w, __ldg(image + p), acc0);
            acc1 = fmaf(w, __ldg(img1 + p),  acc1);
            acc2 = fmaf(w, __ldg(img2 + p),  acc2);
        }
        if (vx1) {
            const float w = ay * ax;
            const int p = row + x1;
            acc0 = fmaf(w, __ldg(image + p), acc0);
            acc1 = fmaf(w, __ldg(img1 + p),  acc1);
            acc2 = fmaf(w, __ldg(img2 + p),  acc2);
        }
    }

    // out [B, C, H, W]: offset = b*3*NN + n = idx + b*2*NN = idx + (b << 13)
    float* ob = out + idx + (b << 13);
    ob[0]      = acc0;
    ob[NN]     = acc1;
    ob[2 * NN] = acc2;
}

extern "C" void kernel_launch(void* const* d_in, const int* in_sizes, int n_in,
                              void* d_out, int out_size)
{
    const float* theta = (const float*)d_in[0];  // [B,1] = 8 floats
    const float* image = (const float*)d_in[1];  // [C,H,W] = 12288 floats
    float* out = (float*)d_out;                  // [B,C,H,W] = 98304 floats

    rotation_bilinear_kernel<<<(BB * NN) / 256, 256>>>(theta, image, out);
}